// round 3
// baseline (speedup 1.0000x reference)
#include <cuda_runtime.h>

#define NPTS    8192
#define NCODES  16384
#define DIM     64

// output layout (floats)
#define OFF_ZQ     0
#define OFF_LOSS   524288
#define OFF_IDX    524289
#define OFF_NUNIQ  532481
#define OFF_USAGE  532482
#define OFF_TOTAL  548866

__device__ int    g_idx[NPTS];
__device__ float  g_b[NCODES];
__device__ float  g_eT[DIM * NCODES];   // transposed codebook [d][k]
__device__ double g_loss;

// ---------------------------------------------------------------------------
// packed f32x2 helpers
// ---------------------------------------------------------------------------
#define FMA2(acc, a, b) \
    asm("fma.rn.f32x2 %0, %1, %2, %0;" : "+l"(acc) : "l"(a), "l"(b))
#define UNPACK2(lo, hi, v) \
    asm("mov.b64 {%0, %1}, %2;" : "=f"(lo), "=f"(hi) : "l"(v))

__device__ __forceinline__ void cp_async16(void* smem_dst, const void* gmem_src) {
    unsigned s = (unsigned)__cvta_generic_to_shared(smem_dst);
    asm volatile("cp.async.cg.shared.global [%0], [%1], 16;" :: "r"(s), "l"(gmem_src));
}
__device__ __forceinline__ void cp_commit() {
    asm volatile("cp.async.commit_group;");
}
__device__ __forceinline__ void cp_wait1() {
    asm volatile("cp.async.wait_group 1;");
}

// ---------------------------------------------------------------------------
// 0) init
// ---------------------------------------------------------------------------
__global__ void vq_init(float* out) {
    int t = blockIdx.x * blockDim.x + threadIdx.x;
    if (t < NCODES) out[OFF_USAGE + t] = 0.0f;
    if (t == 0) g_loss = 0.0;
}

// ---------------------------------------------------------------------------
// 1) transpose codebook [k][d] -> g_eT [d][k]
// ---------------------------------------------------------------------------
__global__ void vq_transpose(const float* __restrict__ emb) {
    __shared__ float t[32][33];
    int kb = blockIdx.x * 32;
    int db = blockIdx.y * 32;
    int x = threadIdx.x, y = threadIdx.y;  // 32 x 8
    for (int yy = y; yy < 32; yy += 8)
        t[yy][x] = emb[(size_t)(kb + yy) * DIM + db + x];
    __syncthreads();
    for (int yy = y; yy < 32; yy += 8)
        g_eT[(size_t)(db + yy) * NCODES + kb + x] = t[x][yy];
}

// ---------------------------------------------------------------------------
// 2) b_k = sum_d e[k][d]^2
// ---------------------------------------------------------------------------
__global__ void vq_codenorm(const float* __restrict__ emb) {
    int k = blockIdx.x * blockDim.x + threadIdx.x;
    if (k >= NCODES) return;
    const float* row = emb + (size_t)k * DIM;
    float s = 0.0f;
#pragma unroll 8
    for (int d = 0; d < DIM; ++d) s = fmaf(row[d], row[d], s);
    g_b[k] = s;
}

// ---------------------------------------------------------------------------
// 3) main argmin kernel
//    512 threads, 64 points x 16384 codes (tiles of 256 codes).
//    8 groups of 64 threads; group g owns points g*8..g*8+7.
//    Thread covers 4 codes (lane64*4..+3) => per-thread tile 8 pts x 4 codes.
//    smem: es double buffer [d][code] (stride 256), zdup [d][2*pos],
//          sb double buffer, sa.
// ---------------------------------------------------------------------------
#define ES_STRIDE  256
#define ES_FLOATS  (64 * ES_STRIDE)           // 16384
#define ZD_FLOATS  (64 * 128)                 // 8192
#define OFF_ES0    0
#define OFF_ES1    ES_FLOATS
#define OFF_ZD     (2 * ES_FLOATS)
#define OFF_SB0    (OFF_ZD + ZD_FLOATS)
#define OFF_SB1    (OFF_SB0 + 256)
#define OFF_SA     (OFF_SB1 + 256)
#define SM_FLOATS  (OFF_SA + 64)

__global__ __launch_bounds__(512, 1)
void vq_argmin(const float* __restrict__ z, float* __restrict__ out) {
    extern __shared__ float smem[];
    float* zdup = smem + OFF_ZD;
    float* sa   = smem + OFF_SA;

    const int tid    = threadIdx.x;
    const int grp    = tid >> 6;        // 0..7, owns points grp*8..+7
    const int lane64 = tid & 63;        // codes lane64*4..+3

    const int pbase   = blockIdx.x * 64;
    const int bb      = pbase >> 10;
    const int posbase = pbase & 1023;

    // ---- prefetch e tile 0 + b tile 0 (async) ----
    {
        float* es = smem + OFF_ES0;
        for (int c = tid; c < 4096; c += 512) {
            int d = c >> 6, ch = c & 63;
            cp_async16(es + d * ES_STRIDE + ch * 4,
                       g_eT + (size_t)d * NCODES + ch * 4);
        }
        if (tid < 64)
            cp_async16(smem + OFF_SB0 + tid * 4, g_b + tid * 4);
        cp_commit();
    }

    // ---- stage z duplicated: zdup[d][2*pos] = zdup[d][2*pos+1] = z ----
    for (int t = tid; t < 64 * 64; t += 512) {
        int d = t >> 6, pos = t & 63;
        float v = z[(size_t)bb * 65536 + (size_t)d * 1024 + posbase + pos];
        *(float2*)(zdup + d * 128 + pos * 2) = make_float2(v, v);
    }
    __syncthreads();

    // a_p = sum_d fl(z^2), strictly sequential d = 0..63
    if (tid < 64) {
        float s = 0.0f;
        for (int d = 0; d < DIM; ++d) {
            float v = zdup[d * 128 + tid * 2];
            s = __fadd_rn(s, __fmul_rn(v, v));
        }
        sa[tid] = s;
    }
    __syncthreads();

    float a_r[8];
#pragma unroll
    for (int i = 0; i < 8; ++i) a_r[i] = sa[grp * 8 + i];

    float bestd[8];
    int   bestk[8];
#pragma unroll
    for (int i = 0; i < 8; ++i) { bestd[i] = __int_as_float(0x7f800000); bestk[i] = 0; }

    const float* zbase = zdup + grp * 16;    // 8 dup-pairs for this group

    for (int tile = 0; tile < NCODES / 256; ++tile) {
        const int cur   = tile & 1;
        const int kbase = tile * 256;

        // prefetch next tile into the other buffer
        if (tile + 1 < NCODES / 256) {
            float* esn = smem + (cur ? OFF_ES0 : OFF_ES1);
            float* sbn = smem + (cur ? OFF_SB0 : OFF_SB1);
            const int kn = kbase + 256;
            for (int c = tid; c < 4096; c += 512) {
                int d = c >> 6, ch = c & 63;
                cp_async16(esn + d * ES_STRIDE + ch * 4,
                           g_eT + (size_t)d * NCODES + kn + ch * 4);
            }
            if (tid < 64)
                cp_async16(sbn + tid * 4, g_b + kn + tid * 4);
        }
        cp_commit();
        cp_wait1();
        __syncthreads();

        const float* es = smem + (cur ? OFF_ES1 : OFF_ES0);
        const float* sb = smem + (cur ? OFF_SB1 : OFF_SB0);

        unsigned long long acc[8][2];
#pragma unroll
        for (int i = 0; i < 8; ++i) { acc[i][0] = 0ULL; acc[i][1] = 0ULL; }

        const ulonglong2* ep = (const ulonglong2*)(es + lane64 * 4);

#pragma unroll 8
        for (int d = 0; d < DIM; ++d) {
            // e: 4 codes = 2 packed pairs, one LDS.128
            ulonglong2 ee = ep[d * (ES_STRIDE / 4)];
            // z: 8 dup-pairs, 4 broadcast LDS.128
            const ulonglong2* zp = (const ulonglong2*)(zbase + d * 128);
            ulonglong2 z01 = zp[0];
            ulonglong2 z23 = zp[1];
            FMA2(acc[0][0], z01.x, ee.x); FMA2(acc[0][1], z01.x, ee.y);
            FMA2(acc[1][0], z01.y, ee.x); FMA2(acc[1][1], z01.y, ee.y);
            FMA2(acc[2][0], z23.x, ee.x); FMA2(acc[2][1], z23.x, ee.y);
            FMA2(acc[3][0], z23.y, ee.x); FMA2(acc[3][1], z23.y, ee.y);
            ulonglong2 z45 = zp[2];
            ulonglong2 z67 = zp[3];
            FMA2(acc[4][0], z45.x, ee.x); FMA2(acc[4][1], z45.x, ee.y);
            FMA2(acc[5][0], z45.y, ee.x); FMA2(acc[5][1], z45.y, ee.y);
            FMA2(acc[6][0], z67.x, ee.x); FMA2(acc[6][1], z67.x, ee.y);
            FMA2(acc[7][0], z67.y, ee.x); FMA2(acc[7][1], z67.y, ee.y);
        }

        // epilogue: dist = fl( fl(a+b) - 2c ); strict < keeps smallest index
        {
            const float4 b4 = *(const float4*)(sb + lane64 * 4);
            const int k0 = kbase + lane64 * 4;
#pragma unroll
            for (int i = 0; i < 8; ++i) {
                float c0, c1, c2, c3;
                UNPACK2(c0, c1, acc[i][0]);
                UNPACK2(c2, c3, acc[i][1]);
                float d0 = fmaf(-2.0f, c0, __fadd_rn(a_r[i], b4.x));
                float d1 = fmaf(-2.0f, c1, __fadd_rn(a_r[i], b4.y));
                float d2 = fmaf(-2.0f, c2, __fadd_rn(a_r[i], b4.z));
                float d3 = fmaf(-2.0f, c3, __fadd_rn(a_r[i], b4.w));
                if (d0 < bestd[i]) { bestd[i] = d0; bestk[i] = k0;     }
                if (d1 < bestd[i]) { bestd[i] = d1; bestk[i] = k0 + 1; }
                if (d2 < bestd[i]) { bestd[i] = d2; bestk[i] = k0 + 2; }
                if (d3 < bestd[i]) { bestd[i] = d3; bestk[i] = k0 + 3; }
            }
        }
        __syncthreads();   // protect es/sb before next prefetch overwrites
    }

    // cross-thread reduction: for point p, candidates live in threads
    // tid in [(p>>3)*64, +64), slot (p&7); tid ascending == code ascending
    float* rd = smem;                         // 4096 floats
    int*   ri = (int*)(smem + 4096);          // 4096 ints
#pragma unroll
    for (int i = 0; i < 8; ++i) {
        rd[tid * 8 + i] = bestd[i];
        ri[tid * 8 + i] = bestk[i];
    }
    __syncthreads();

    if (tid < 64) {
        int p  = tid;
        int mg = p >> 3;
        int mi = p & 7;
        float bd = __int_as_float(0x7f800000);
        int   bk = 0x7fffffff;
        for (int c = 0; c < 64; ++c) {
            int   t2 = (mg * 64 + c) * 8 + mi;
            float dd = rd[t2];
            int   kk = ri[t2];
            if (dd < bd || (dd == bd && kk < bk)) { bd = dd; bk = kk; }
        }
        g_idx[pbase + p] = bk;
        out[OFF_IDX + pbase + p] = (float)bk;
        out[OFF_USAGE + bk] = 1.0f;
    }
}

// ---------------------------------------------------------------------------
// 4) z_q gather + loss accumulation
// ---------------------------------------------------------------------------
__global__ void vq_zq_loss(const float* __restrict__ z,
                           const float* __restrict__ emb,
                           float* __restrict__ out) {
    __shared__ double sd[256];
    double acc = 0.0;
    for (int g = blockIdx.x * 256 + threadIdx.x; g < 524288; g += 65536) {
        int d   = (g >> 10) & 63;
        int bb  = g >> 16;
        int pos = g & 1023;
        int k   = g_idx[bb * 1024 + pos];
        float e  = emb[(size_t)k * DIM + d];
        float zv = z[g];
        out[OFF_ZQ + g] = e;
        float diff = e - zv;
        acc += (double)diff * (double)diff;
    }
    sd[threadIdx.x] = acc;
    __syncthreads();
    for (int s = 128; s > 0; s >>= 1) {
        if (threadIdx.x < s) sd[threadIdx.x] += sd[threadIdx.x + s];
        __syncthreads();
    }
    if (threadIdx.x == 0) atomicAdd(&g_loss, sd[0]);
}

// ---------------------------------------------------------------------------
// 5) finalize
// ---------------------------------------------------------------------------
__global__ void vq_finalize(float* out) {
    __shared__ float sf[512];
    float s = 0.0f;
    for (int t = threadIdx.x; t < NCODES; t += 512) s += out[OFF_USAGE + t];
    sf[threadIdx.x] = s;
    __syncthreads();
    for (int st = 256; st > 0; st >>= 1) {
        if (threadIdx.x < st) sf[threadIdx.x] += sf[threadIdx.x + st];
        __syncthreads();
    }
    if (threadIdx.x == 0) {
        float total = sf[0];
        out[OFF_NUNIQ] = total;
        out[OFF_TOTAL] = total / (float)NCODES;
        float m = (float)(g_loss / 524288.0);
        out[OFF_LOSS] = m + 0.25f * m;
    }
}

// ---------------------------------------------------------------------------
extern "C" void kernel_launch(void* const* d_in, const int* in_sizes, int n_in,
                              void* d_out, int out_size) {
    const float* z;
    const float* emb;
    if (in_sizes[0] == 524288) {
        z = (const float*)d_in[0];
        emb = (const float*)d_in[1];
    } else {
        z = (const float*)d_in[1];
        emb = (const float*)d_in[0];
    }
    float* out = (float*)d_out;

    static int attr_set = 0;
    if (!attr_set) {
        cudaFuncSetAttribute(vq_argmin, cudaFuncAttributeMaxDynamicSharedMemorySize,
                             SM_FLOATS * (int)sizeof(float));
        attr_set = 1;
    }

    vq_init<<<(NCODES + 255) / 256, 256>>>(out);
    vq_transpose<<<dim3(NCODES / 32, DIM / 32), dim3(32, 8)>>>(emb);
    vq_codenorm<<<(NCODES + 255) / 256, 256>>>(emb);
    vq_argmin<<<NPTS / 64, 512, SM_FLOATS * sizeof(float)>>>(z, out);
    vq_zq_loss<<<256, 256>>>(z, emb, out);
    vq_finalize<<<1, 512>>>(out);
}

// round 4
// speedup vs baseline: 1.1944x; 1.1944x over previous
#include <cuda_runtime.h>

#define NPTS    8192
#define NCODES  16384
#define DIM     64

#define PB      32            // points per block
#define CT      512           // codes per tile
#define CHD     8             // d-rows per chunk
#define NCHUNK  ((NCODES / CT) * (DIM / CHD))   // 32 tiles * 8 phases = 256
#define RING    4

// output layout (floats)
#define OFF_ZQ     0
#define OFF_LOSS   524288
#define OFF_IDX    524289
#define OFF_NUNIQ  532481
#define OFF_USAGE  532482
#define OFF_TOTAL  548866

__device__ int    g_idx[NPTS];
__device__ float  g_b[NCODES];
__device__ float  g_eT[DIM * NCODES];   // transposed codebook [d][k]
__device__ double g_loss;

// ---------------------------------------------------------------------------
// packed f32x2 helpers
// ---------------------------------------------------------------------------
#define PACK_DUP(dst, f) \
    asm("mov.b64 %0, {%1, %1};" : "=l"(dst) : "f"(f))
#define FMA2(acc, a, b) \
    asm("fma.rn.f32x2 %0, %1, %2, %0;" : "+l"(acc) : "l"(a), "l"(b))
#define UNPACK2(lo, hi, v) \
    asm("mov.b64 {%0, %1}, %2;" : "=f"(lo), "=f"(hi) : "l"(v))

__device__ __forceinline__ void cp_async16(void* smem_dst, const void* gmem_src) {
    unsigned s = (unsigned)__cvta_generic_to_shared(smem_dst);
    asm volatile("cp.async.cg.shared.global [%0], [%1], 16;" :: "r"(s), "l"(gmem_src));
}
__device__ __forceinline__ void cp_commit() {
    asm volatile("cp.async.commit_group;");
}
__device__ __forceinline__ void cp_wait2() {
    asm volatile("cp.async.wait_group 2;");
}

// ---------------------------------------------------------------------------
// 0) init
// ---------------------------------------------------------------------------
__global__ void vq_init(float* out) {
    int t = blockIdx.x * blockDim.x + threadIdx.x;
    if (t < NCODES) out[OFF_USAGE + t] = 0.0f;
    if (t == 0) g_loss = 0.0;
}

// ---------------------------------------------------------------------------
// 1) transpose codebook [k][d] -> g_eT [d][k]
// ---------------------------------------------------------------------------
__global__ void vq_transpose(const float* __restrict__ emb) {
    __shared__ float t[32][33];
    int kb = blockIdx.x * 32;
    int db = blockIdx.y * 32;
    int x = threadIdx.x, y = threadIdx.y;  // 32 x 8
    for (int yy = y; yy < 32; yy += 8)
        t[yy][x] = emb[(size_t)(kb + yy) * DIM + db + x];
    __syncthreads();
    for (int yy = y; yy < 32; yy += 8)
        g_eT[(size_t)(db + yy) * NCODES + kb + x] = t[x][yy];
}

// ---------------------------------------------------------------------------
// 2) b_k = sum_d e[k][d]^2
// ---------------------------------------------------------------------------
__global__ void vq_codenorm(const float* __restrict__ emb) {
    int k = blockIdx.x * blockDim.x + threadIdx.x;
    if (k >= NCODES) return;
    const float* row = emb + (size_t)k * DIM;
    float s = 0.0f;
#pragma unroll 8
    for (int d = 0; d < DIM; ++d) s = fmaf(row[d], row[d], s);
    g_b[k] = s;
}

// ---------------------------------------------------------------------------
// 3) main argmin kernel
//    256 threads, 2 CTAs/SM. 32 points x 16384 codes.
//    Structure: 4 point-groups (8 pts) x 64 code-lanes.
//    Thread tile: 8 pts x 8 codes (codes 4*l64..+3 and 4*l64+256..+3 in tile).
//    es: 4-deep ring of (8 d-rows x 512 codes) chunks, cp.async 3 ahead.
// ---------------------------------------------------------------------------
#define ES_FLOATS   (RING * CHD * CT)   // 16384
#define ZS_STRIDE   36
#define ZS_FLOATS   (DIM * ZS_STRIDE)   // 2304
#define OFF_ES      0
#define OFF_ZS      ES_FLOATS
#define OFF_SBB     (OFF_ZS + ZS_FLOATS)
#define OFF_SA      (OFF_SBB + 2 * CT)
#define SM_FLOATS   (OFF_SA + PB)       // 19744 floats = 78976 B

__device__ __forceinline__ void issue_chunk(float* es, float* sb, int idx, int tid) {
    const int slot = idx & (RING - 1);
    const int tile = idx >> 3;
    const int d0   = (idx & 7) * CHD;
#pragma unroll
    for (int i = 0; i < 4; ++i) {
        int u   = tid + i * 256;      // 1024 units of 16B
        int row = u >> 7;             // 0..7
        int col = (u & 127) * 4;      // float col 0..508
        cp_async16(es + slot * (CHD * CT) + row * CT + col,
                   g_eT + (size_t)(d0 + row) * NCODES + tile * CT + col);
    }
    if ((idx & 7) == 0 && tid < 128) {
        cp_async16(sb + (tile & 1) * CT + tid * 4, g_b + tile * CT + tid * 4);
    }
}

__global__ __launch_bounds__(256, 2)
void vq_argmin(const float* __restrict__ z, float* __restrict__ out) {
    extern __shared__ float smem[];
    float* es = smem + OFF_ES;
    float* zs = smem + OFF_ZS;
    float* sb = smem + OFF_SBB;
    float* sa = smem + OFF_SA;

    const int tid = threadIdx.x;
    const int grp = tid >> 6;          // 0..3 : points grp*8..+7
    const int l64 = tid & 63;          // codes 4*l64 and 4*l64+256 within tile

    const int pbase   = blockIdx.x * PB;
    const int bb      = pbase >> 10;
    const int posbase = pbase & 1023;

    // prologue: 3 chunks in flight
    issue_chunk(es, sb, 0, tid); cp_commit();
    issue_chunk(es, sb, 1, tid); cp_commit();
    issue_chunk(es, sb, 2, tid); cp_commit();

    // stage z: zs[d][pos], pos < 32
    for (int t = tid; t < DIM * PB; t += 256) {
        int d = t >> 5, pos = t & 31;
        zs[d * ZS_STRIDE + pos] =
            z[(size_t)bb * 65536 + (size_t)d * 1024 + posbase + pos];
    }
    __syncthreads();

    // a_p = sum_d fl(z^2), strictly sequential d (match jnp.sum order)
    if (tid < PB) {
        float s = 0.0f;
        for (int d = 0; d < DIM; ++d) {
            float v = zs[d * ZS_STRIDE + tid];
            s = __fadd_rn(s, __fmul_rn(v, v));
        }
        sa[tid] = s;
    }
    __syncthreads();

    float a_r[8];
#pragma unroll
    for (int i = 0; i < 8; ++i) a_r[i] = sa[grp * 8 + i];

    float bestd[8];
    int   bestk[8];
#pragma unroll
    for (int i = 0; i < 8; ++i) { bestd[i] = __int_as_float(0x7f800000); bestk[i] = 0; }

    unsigned long long acc[8][4];
#pragma unroll
    for (int i = 0; i < 8; ++i)
#pragma unroll
        for (int j = 0; j < 4; ++j) acc[i][j] = 0ULL;

    const float* zbase = zs + grp * 8;

    for (int c = 0; c < NCHUNK; ++c) {
        cp_wait2();            // chunk c's group retired
        __syncthreads();       // all threads' pieces of chunk c visible;
                               // also: everyone done with chunk c-1 (slot of c+3)
        if (c + 3 < NCHUNK) issue_chunk(es, sb, c + 3, tid);
        cp_commit();           // always commit (possibly empty group)

        const float* ebase = es + (c & (RING - 1)) * (CHD * CT) + l64 * 4;
        const int d0 = (c & 7) * CHD;

#pragma unroll 4
        for (int dd = 0; dd < CHD; ++dd) {
            const float* zrow = zbase + (d0 + dd) * ZS_STRIDE;
            const float4 za = *(const float4*)(zrow);
            const float4 zb = *(const float4*)(zrow + 4);
            unsigned long long zz[8];
            PACK_DUP(zz[0], za.x); PACK_DUP(zz[1], za.y);
            PACK_DUP(zz[2], za.z); PACK_DUP(zz[3], za.w);
            PACK_DUP(zz[4], zb.x); PACK_DUP(zz[5], zb.y);
            PACK_DUP(zz[6], zb.z); PACK_DUP(zz[7], zb.w);

            const float* erow = ebase + dd * CT;
            const ulonglong2 eA = *(const ulonglong2*)(erow);
            const ulonglong2 eB = *(const ulonglong2*)(erow + 256);

#pragma unroll
            for (int i = 0; i < 8; ++i) {
                FMA2(acc[i][0], zz[i], eA.x);
                FMA2(acc[i][1], zz[i], eA.y);
                FMA2(acc[i][2], zz[i], eB.x);
                FMA2(acc[i][3], zz[i], eB.y);
            }
        }

        if ((c & 7) == 7) {
            // tile epilogue: dist = fl( fl(a+b) - 2c ), ascending k in-thread
            const int tile  = c >> 3;
            const int kbase = tile * CT;
            const float* sbc = sb + (tile & 1) * CT + l64 * 4;
            const float4 bA = *(const float4*)(sbc);
            const float4 bB = *(const float4*)(sbc + 256);
            const int kA = kbase + l64 * 4;
            const int kB = kA + 256;
#pragma unroll
            for (int i = 0; i < 8; ++i) {
                float c0, c1, c2, c3;
                UNPACK2(c0, c1, acc[i][0]);
                UNPACK2(c2, c3, acc[i][1]);
                float d0v = fmaf(-2.0f, c0, __fadd_rn(a_r[i], bA.x));
                float d1v = fmaf(-2.0f, c1, __fadd_rn(a_r[i], bA.y));
                float d2v = fmaf(-2.0f, c2, __fadd_rn(a_r[i], bA.z));
                float d3v = fmaf(-2.0f, c3, __fadd_rn(a_r[i], bA.w));
                if (d0v < bestd[i]) { bestd[i] = d0v; bestk[i] = kA;     }
                if (d1v < bestd[i]) { bestd[i] = d1v; bestk[i] = kA + 1; }
                if (d2v < bestd[i]) { bestd[i] = d2v; bestk[i] = kA + 2; }
                if (d3v < bestd[i]) { bestd[i] = d3v; bestk[i] = kA + 3; }
                UNPACK2(c0, c1, acc[i][2]);
                UNPACK2(c2, c3, acc[i][3]);
                d0v = fmaf(-2.0f, c0, __fadd_rn(a_r[i], bB.x));
                d1v = fmaf(-2.0f, c1, __fadd_rn(a_r[i], bB.y));
                d2v = fmaf(-2.0f, c2, __fadd_rn(a_r[i], bB.z));
                d3v = fmaf(-2.0f, c3, __fadd_rn(a_r[i], bB.w));
                if (d0v < bestd[i]) { bestd[i] = d0v; bestk[i] = kB;     }
                if (d1v < bestd[i]) { bestd[i] = d1v; bestk[i] = kB + 1; }
                if (d2v < bestd[i]) { bestd[i] = d2v; bestk[i] = kB + 2; }
                if (d3v < bestd[i]) { bestd[i] = d3v; bestk[i] = kB + 3; }
                acc[i][0] = 0ULL; acc[i][1] = 0ULL;
                acc[i][2] = 0ULL; acc[i][3] = 0ULL;
            }
        }
    }

    // cross-thread reduction with explicit (d, k) lexicographic min
    __syncthreads();
    float* rd = smem;                       // 2048 floats (reuse es)
    int*   ri = (int*)(smem + 2048);        // 2048 ints
#pragma unroll
    for (int i = 0; i < 8; ++i) {
        rd[tid * 8 + i] = bestd[i];
        ri[tid * 8 + i] = bestk[i];
    }
    __syncthreads();

    if (tid < PB) {
        int p  = tid;
        int mg = p >> 3;
        int mi = p & 7;
        float bd = __int_as_float(0x7f800000);
        int   bk = 0x7fffffff;
        for (int t = 0; t < 64; ++t) {
            int   t2 = (mg * 64 + t) * 8 + mi;
            float dd = rd[t2];
            int   kk = ri[t2];
            if (dd < bd || (dd == bd && kk < bk)) { bd = dd; bk = kk; }
        }
        g_idx[pbase + p] = bk;
        out[OFF_IDX + pbase + p] = (float)bk;
        out[OFF_USAGE + bk] = 1.0f;          // idempotent scatter
    }
}

// ---------------------------------------------------------------------------
// 4) z_q gather + loss accumulation
// ---------------------------------------------------------------------------
__global__ void vq_zq_loss(const float* __restrict__ z,
                           const float* __restrict__ emb,
                           float* __restrict__ out) {
    __shared__ double sd[256];
    double acc = 0.0;
    for (int g = blockIdx.x * 256 + threadIdx.x; g < 524288; g += 65536) {
        int d   = (g >> 10) & 63;
        int bb  = g >> 16;
        int pos = g & 1023;
        int k   = g_idx[bb * 1024 + pos];
        float e  = emb[(size_t)k * DIM + d];
        float zv = z[g];
        out[OFF_ZQ + g] = e;
        float diff = e - zv;
        acc += (double)diff * (double)diff;
    }
    sd[threadIdx.x] = acc;
    __syncthreads();
    for (int s = 128; s > 0; s >>= 1) {
        if (threadIdx.x < s) sd[threadIdx.x] += sd[threadIdx.x + s];
        __syncthreads();
    }
    if (threadIdx.x == 0) atomicAdd(&g_loss, sd[0]);
}

// ---------------------------------------------------------------------------
// 5) finalize
// ---------------------------------------------------------------------------
__global__ void vq_finalize(float* out) {
    __shared__ float sf[512];
    float s = 0.0f;
    for (int t = threadIdx.x; t < NCODES; t += 512) s += out[OFF_USAGE + t];
    sf[threadIdx.x] = s;
    __syncthreads();
    for (int st = 256; st > 0; st >>= 1) {
        if (threadIdx.x < st) sf[threadIdx.x] += sf[threadIdx.x + st];
        __syncthreads();
    }
    if (threadIdx.x == 0) {
        float total = sf[0];
        out[OFF_NUNIQ] = total;
        out[OFF_TOTAL] = total / (float)NCODES;
        float m = (float)(g_loss / 524288.0);
        out[OFF_LOSS] = m + 0.25f * m;
    }
}

// ---------------------------------------------------------------------------
extern "C" void kernel_launch(void* const* d_in, const int* in_sizes, int n_in,
                              void* d_out, int out_size) {
    const float* z;
    const float* emb;
    if (in_sizes[0] == 524288) {
        z = (const float*)d_in[0];
        emb = (const float*)d_in[1];
    } else {
        z = (const float*)d_in[1];
        emb = (const float*)d_in[0];
    }
    float* out = (float*)d_out;

    static int attr_set = 0;
    if (!attr_set) {
        cudaFuncSetAttribute(vq_argmin, cudaFuncAttributeMaxDynamicSharedMemorySize,
                             SM_FLOATS * (int)sizeof(float));
        attr_set = 1;
    }

    vq_init<<<(NCODES + 255) / 256, 256>>>(out);
    vq_transpose<<<dim3(NCODES / 32, DIM / 32), dim3(32, 8)>>>(emb);
    vq_codenorm<<<(NCODES + 255) / 256, 256>>>(emb);
    vq_argmin<<<NPTS / PB, 256, SM_FLOATS * sizeof(float)>>>(z, out);
    vq_zq_loss<<<256, 256>>>(z, emb, out);
    vq_finalize<<<1, 512>>>(out);
}